// round 7
// baseline (speedup 1.0000x reference)
#include <cuda_runtime.h>

#define IMG   64
#define CH    16
#define B     8
#define N_PIX 4096   // 64*64

// ---------------- scratch (no allocations allowed) ----------------
__device__ float g_buf0[B * CH * N_PIX];
__device__ float g_buf1[B * CH * N_PIX];
__device__ float g_xc  [B * CH * N_PIX];   // pre-scaled: (x - mean) * invstd * 0.25

// packed conv weights, pair = {w[2*ocp], w[2*ocp+1]} for (ic,ky,kx)
__device__ unsigned long long g_w1pa[8 * 16 * 5 * 4];
__device__ unsigned long long g_w1pb[8 * 16 * 5];
__device__ unsigned long long g_w2pa[8 * 16 * 5 * 4];
__device__ unsigned long long g_w2pb[8 * 16 * 5];
__device__ unsigned long long g_b1p[8];
__device__ unsigned long long g_b2p[8];

#define FMA2(acc, a, b)  asm("fma.rn.f32x2 %0, %1, %2, %0;" : "+l"(acc) : "l"(a), "l"(b))
#define ADD2(acc, a)     asm("add.rn.f32x2 %0, %0, %1;" : "+l"(acc) : "l"(a))
#define DUP2(p, v)       asm("mov.b64 %0, {%1, %1};" : "=l"(p) : "f"(v))
#define PACK2(p, lo, hi) asm("mov.b64 %0, {%1, %2};" : "=l"(p) : "f"(lo), "f"(hi))
#define UNPK2(lo, hi, p) asm("mov.b64 {%0, %1}, %2;" : "=f"(lo), "=f"(hi) : "l"(p))
#define STG_CS4(ptr, a, b, c, d) \
    asm volatile("st.global.cs.v4.f32 [%0], {%1, %2, %3, %4};" \
                 :: "l"(ptr), "f"(a), "f"(b), "f"(c), "f"(d))

// ---------------- conv0 (1->16ch) + weight-pair packing fused ----------------
__global__ void conv0_kernel(const float* __restrict__ x,
                             const float* __restrict__ w,
                             const float* __restrict__ bias,
                             const float* __restrict__ w1, const float* __restrict__ b1,
                             const float* __restrict__ w2, const float* __restrict__ b2) {
    int id = blockIdx.x * blockDim.x + threadIdx.x;

    if (blockIdx.x < 26) {
        int idx = id;
        if (idx < 6400) {
            int which = idx >= 3200;
            int r = which ? idx - 3200 : idx;
            int kx = r % 5;
            int g  = r / 5;
            int ocic = g / 5;
            int ic  = ocic & 15;
            int ocp = ocic >> 4;
            int ky  = g % 5;
            const float* wsrc = which ? w2 : w1;
            float lo = wsrc[(2 * ocp) * 400 + ic * 25 + ky * 5 + kx];
            float hi = wsrc[(2 * ocp + 1) * 400 + ic * 25 + ky * 5 + kx];
            unsigned long long p;
            PACK2(p, lo, hi);
            if (kx < 4) { (which ? g_w2pa : g_w1pa)[g * 4 + kx] = p; }
            else        { (which ? g_w2pb : g_w1pb)[g]          = p; }
        } else if (idx < 6416) {
            int k = idx - 6400;
            int which = k >= 8;
            int p = k & 7;
            const float* bb = which ? b2 : b1;
            unsigned long long pr;
            PACK2(pr, bb[2 * p], bb[2 * p + 1]);
            (which ? g_b2p : g_b1p)[p] = pr;
        }
    }

    int pix = id & 4095;
    int oc  = (id >> 12) & 15;
    int b   = id >> 16;
    int py = pix >> 6, px = pix & 63;
    const float* xin = x + b * N_PIX;
    float acc = __ldg(bias + oc);
    #pragma unroll
    for (int ky = 0; ky < 5; ky++) {
        int gy = py + ky - 2;
        if (gy < 0 || gy >= IMG) continue;
        #pragma unroll
        for (int kx = 0; kx < 5; kx++) {
            int gx = px + kx - 2;
            if (gx < 0 || gx >= IMG) continue;
            acc = fmaf(xin[gy * IMG + gx], __ldg(w + oc * 25 + ky * 5 + kx), acc);
        }
    }
    g_buf0[id] = acc;
}

// ---------------- conv16: 256 threads = 4 ic-groups x (32x2 tile), grid (64,B) ----------------
template<bool FUSE>
__global__ void __launch_bounds__(256) conv16s_kernel() {
    __shared__ __align__(16) char smraw[39424];
    float* sin_t            = (float*)smraw;                         // 13824 B (16ch x 6 x 36)
    unsigned long long* swa = (unsigned long long*)(smraw + 13824);  // 20480 B
    unsigned long long* swb = (unsigned long long*)(smraw + 34304);  //  5120 B
    unsigned long long* sred = (unsigned long long*)(smraw + 13824); // overlay 12288 B

    const float* in = FUSE ? g_buf1 : g_buf0;
    const unsigned long long* gwa = FUSE ? g_w2pa : g_w1pa;
    const unsigned long long* gwb = FUSE ? g_w2pb : g_w1pb;
    const unsigned long long* gbp = FUSE ? g_b2p  : g_b1p;

    int tid  = threadIdx.x;
    int tile = blockIdx.x;                   // 0..63
    int b    = blockIdx.y;
    int tx0  = (tile & 1) * 32;
    int ty0  = (tile >> 1) * 2;

    for (int i = tid; i < 8 * 16 * 5 * 4; i += 256) swa[i] = gwa[i];
    for (int i = tid; i < 8 * 16 * 5;     i += 256) swb[i] = gwb[i];

    const float* inb = in + b * CH * N_PIX;
    for (int idx = tid; idx < CH * 6 * 36; idx += 256) {
        int c   = idx / 216;
        int rem = idx - c * 216;
        int r   = rem / 36;
        int cc  = rem - r * 36;
        int gy = ty0 + r - 2;
        int gx = tx0 + cc - 2;
        float v = 0.f;
        if (gy >= 0 && gy < IMG && gx >= 0 && gx < IMG)
            v = inb[c * N_PIX + gy * IMG + gx];
        sin_t[idx] = v;
    }
    __syncthreads();

    int grp = tid >> 6;         // 0..3: which 4 input channels
    int wg  = tid & 63;
    int tx = wg & 31, ty = wg >> 5;   // ty 0..1

    unsigned long long acc[8];
    #pragma unroll
    for (int p = 0; p < 8; p++) acc[p] = 0ULL;

    #pragma unroll
    for (int icl = 0; icl < 4; icl++) {
        int ic = grp * 4 + icl;
        const float* srow = &sin_t[ic * 216 + ty * 36 + tx];
        #pragma unroll
        for (int ky = 0; ky < 5; ky++) {
            const float* rr = srow + ky * 36;
            unsigned long long pa0, pa1, pa2, pa3, pa4;
            DUP2(pa0, rr[0]); DUP2(pa1, rr[1]); DUP2(pa2, rr[2]);
            DUP2(pa3, rr[3]); DUP2(pa4, rr[4]);
            #pragma unroll
            for (int p = 0; p < 8; p++) {
                int g = (p * 16 + ic) * 5 + ky;
                const ulonglong2* wq = reinterpret_cast<const ulonglong2*>(&swa[g * 4]);
                ulonglong2 q0 = wq[0];
                ulonglong2 q1 = wq[1];
                unsigned long long w4 = swb[g];
                FMA2(acc[p], pa0, q0.x);
                FMA2(acc[p], pa1, q0.y);
                FMA2(acc[p], pa2, q1.x);
                FMA2(acc[p], pa3, q1.y);
                FMA2(acc[p], pa4, w4);
            }
        }
    }

    __syncthreads();   // weights dead before overlay
    if (grp > 0) {
        #pragma unroll
        for (int p = 0; p < 8; p++)
            sred[p * 192 + (grp - 1) * 64 + wg] = acc[p];
    }
    __syncthreads();

    if (grp == 0) {
        #pragma unroll
        for (int p = 0; p < 8; p++) {
            ADD2(acc[p], sred[p * 192 + wg]);
            ADD2(acc[p], sred[p * 192 + 64 + wg]);
            ADD2(acc[p], sred[p * 192 + 128 + wg]);
            ADD2(acc[p], gbp[p]);
        }

        int py = ty0 + ty, px = tx0 + tx;
        int pix = py * IMG + px;

        if (!FUSE) {
            float* outb = g_buf1 + b * CH * N_PIX + pix;
            #pragma unroll
            for (int p = 0; p < 8; p++) {
                float lo, hi;
                UNPK2(lo, hi, acc[p]);
                outb[(2 * p) * N_PIX]     = lo;
                outb[(2 * p + 1) * N_PIX] = hi;
            }
        } else {
            // fused stats + pre-scale: xc' = (v - mean) * invstd * 0.25
            float v[16];
            float s = 0.f;
            #pragma unroll
            for (int p = 0; p < 8; p++) {
                UNPK2(v[2 * p], v[2 * p + 1], acc[p]);
                s += v[2 * p] + v[2 * p + 1];
            }
            float mean = s * (1.f / 16.f);
            float var = 0.f;
            #pragma unroll
            for (int c = 0; c < 16; c++) {
                float d = v[c] - mean;
                v[c] = d;
                var = fmaf(d, d, var);
            }
            var *= (1.f / 15.f);                 // ddof = 1
            float sc = rsqrtf(var) * 0.25f;      // 0.25^2 folds the /16
            float* xcb = g_xc + b * CH * N_PIX + pix;
            #pragma unroll
            for (int c = 0; c < 16; c++)
                xcb[c * N_PIX] = v[c] * sc;
        }
    }
}

// ---------------- coupling v3: per-(ti,tj) block, 8-batch loop, mask in registers ----------------
// out[b,i,j] = (xc'_i . xc'_j) * mask   (xc' pre-scaled).  tj >= ti only; mirror via
// conflict-free float4 staging (17-float4 row stride + write-phase lane rotation).
__global__ void __launch_bounds__(256, 3) coupling_kernel(const float* __restrict__ mask,
                                                          float* __restrict__ out) {
    __shared__ __align__(16) float sxi[16 * 64];
    __shared__ __align__(16) float sxj[16 * 64];
    __shared__ __align__(16) float4 stg4[64 * 17];   // [jrow][icolgrp], stride 17

    int p = blockIdx.x;             // 0..2079 triangular pair index (T=64)
    int ti = (int)((129.0f - sqrtf(129.0f * 129.0f - 8.0f * (float)p)) * 0.5f);
    while (((ti + 1) * 64 - ((ti + 1) * ti) / 2) <= p) ti++;
    while ((ti * 64 - (ti * (ti - 1)) / 2) > p) ti--;
    int tj = ti + (p - (ti * 64 - (ti * (ti - 1)) / 2));
    bool diag = (ti == tj);

    int tid = threadIdx.x;
    int txj = tid & 15, tyi = tid >> 4;
    int jl = txj * 4, il = tyi * 4;

    // mask tiles -> registers, reused for all 8 batches
    float4 mf[4];                   // forward: rows ti*64+il+ii, cols tj*64+jl
    float4 mm[4];                   // mirror:  rows tj*64+il+rr, cols ti*64+jl
    #pragma unroll
    for (int ii = 0; ii < 4; ii++)
        mf[ii] = *reinterpret_cast<const float4*>(
            mask + (size_t)(ti * 64 + il + ii) * N_PIX + tj * 64 + jl);
    if (!diag) {
        #pragma unroll
        for (int rr = 0; rr < 4; rr++)
            mm[rr] = *reinterpret_cast<const float4*>(
                mask + (size_t)(tj * 64 + il + rr) * N_PIX + ti * 64 + jl);
    }

    for (int b = 0; b < B; b++) {
        const float* xcb = g_xc + b * CH * N_PIX;
        #pragma unroll
        for (int it = 0; it < 2; it++) {
            int i = it * 256 + tid;
            int which = i >> 8;
            int k = i & 255;
            int c = k >> 4, q = k & 15;
            int t0 = which ? tj : ti;
            float4 v = *reinterpret_cast<const float4*>(xcb + c * N_PIX + t0 * 64 + q * 4);
            (which ? reinterpret_cast<float4*>(sxj) : reinterpret_cast<float4*>(sxi))[k] = v;
        }
        __syncthreads();

        unsigned long long a0[4], a1[4];
        #pragma unroll
        for (int ii = 0; ii < 4; ii++) { a0[ii] = 0ULL; a1[ii] = 0ULL; }

        #pragma unroll
        for (int c = 0; c < 16; c++) {
            float4 av = *reinterpret_cast<const float4*>(&sxi[c * 64 + il]);
            ulonglong2 bq = *reinterpret_cast<const ulonglong2*>(&sxj[c * 64 + jl]);
            unsigned long long pa;
            DUP2(pa, av.x); FMA2(a0[0], pa, bq.x); FMA2(a1[0], pa, bq.y);
            DUP2(pa, av.y); FMA2(a0[1], pa, bq.x); FMA2(a1[1], pa, bq.y);
            DUP2(pa, av.z); FMA2(a0[2], pa, bq.x); FMA2(a1[2], pa, bq.y);
            DUP2(pa, av.w); FMA2(a0[3], pa, bq.x); FMA2(a1[3], pa, bq.y);
        }

        float v[4][4];
        #pragma unroll
        for (int ii = 0; ii < 4; ii++) {
            UNPK2(v[ii][0], v[ii][1], a0[ii]);
            UNPK2(v[ii][2], v[ii][3], a1[ii]);
        }

        size_t obase = (size_t)b * N_PIX * N_PIX;

        // forward stores (masked)
        #pragma unroll
        for (int ii = 0; ii < 4; ii++) {
            float* orow = out + obase + (size_t)(ti * 64 + il + ii) * N_PIX + tj * 64 + jl;
            STG_CS4(orow, v[ii][0] * mf[ii].x, v[ii][1] * mf[ii].y,
                          v[ii][2] * mf[ii].z, v[ii][3] * mf[ii].w);
        }

        if (!diag) {
            // staging: transposed float4 rows, lane-rotated for conflict-free phases
            #pragma unroll
            for (int k = 0; k < 4; k++) {
                int jj = (k + (txj >> 1)) & 3;
                stg4[(jl + jj) * 17 + tyi] =
                    make_float4(v[0][jj], v[1][jj], v[2][jj], v[3][jj]);
            }
            __syncthreads();
            // mirror: rows tj*64+il+rr, cols ti*64+jl (coalesced)
            #pragma unroll
            for (int rr = 0; rr < 4; rr++) {
                float4 s = stg4[(il + rr) * 17 + txj];
                float* orow = out + obase + (size_t)(tj * 64 + il + rr) * N_PIX + ti * 64 + jl;
                STG_CS4(orow, s.x * mm[rr].x, s.y * mm[rr].y,
                              s.z * mm[rr].z, s.w * mm[rr].w);
            }
        }
        __syncthreads();   // protect sxi/sxj (and stg) before next batch refill
    }
}

// ---------------- launch ----------------
extern "C" void kernel_launch(void* const* d_in, const int* in_sizes, int n_in,
                              void* d_out, int out_size) {
    const float* x    = (const float*)d_in[0];
    const float* w0   = (const float*)d_in[1];
    const float* b0   = (const float*)d_in[2];
    const float* w1   = (const float*)d_in[3];
    const float* b1   = (const float*)d_in[4];
    const float* w2   = (const float*)d_in[5];
    const float* b2   = (const float*)d_in[6];
    const float* mask = (const float*)d_in[7];
    float* out = (float*)d_out;

    conv0_kernel<<<(B * CH * N_PIX) / 256, 256>>>(x, w0, b0, w1, b1, w2, b2);
    conv16s_kernel<false><<<dim3(64, B), 256>>>();      // g_buf0 -> g_buf1
    conv16s_kernel<true ><<<dim3(64, B), 256>>>();      // g_buf1 -> g_xc (pre-scaled)
    coupling_kernel<<<2080, 256>>>(mask, out);          // -> d_out
}

// round 8
// speedup vs baseline: 1.0495x; 1.0495x over previous
#include <cuda_runtime.h>

#define IMG   64
#define CH    16
#define B     8
#define N_PIX 4096   // 64*64

// ---------------- scratch (no allocations allowed) ----------------
__device__ float g_buf0[B * CH * N_PIX];
__device__ float g_buf1[B * CH * N_PIX];
__device__ float g_xc  [B * CH * N_PIX];   // pre-scaled: (x - mean) * invstd * 0.25

// packed conv weights, pair = {w[2*ocp], w[2*ocp+1]} for (ic,ky,kx)
__device__ unsigned long long g_w1pa[8 * 16 * 5 * 4];
__device__ unsigned long long g_w1pb[8 * 16 * 5];
__device__ unsigned long long g_w2pa[8 * 16 * 5 * 4];
__device__ unsigned long long g_w2pb[8 * 16 * 5];
__device__ unsigned long long g_b1p[8];
__device__ unsigned long long g_b2p[8];

#define FMA2(acc, a, b)  asm("fma.rn.f32x2 %0, %1, %2, %0;" : "+l"(acc) : "l"(a), "l"(b))
#define ADD2(acc, a)     asm("add.rn.f32x2 %0, %0, %1;" : "+l"(acc) : "l"(a))
#define DUP2(p, v)       asm("mov.b64 %0, {%1, %1};" : "=l"(p) : "f"(v))
#define PACK2(p, lo, hi) asm("mov.b64 %0, {%1, %2};" : "=l"(p) : "f"(lo), "f"(hi))
#define UNPK2(lo, hi, p) asm("mov.b64 {%0, %1}, %2;" : "=f"(lo), "=f"(hi) : "l"(p))
#define STG_CS4(ptr, a, b, c, d) \
    asm volatile("st.global.cs.v4.f32 [%0], {%1, %2, %3, %4};" \
                 :: "l"(ptr), "f"(a), "f"(b), "f"(c), "f"(d))

// ---------------- conv0 (1->16ch) + weight-pair packing fused ----------------
__global__ void conv0_kernel(const float* __restrict__ x,
                             const float* __restrict__ w,
                             const float* __restrict__ bias,
                             const float* __restrict__ w1, const float* __restrict__ b1,
                             const float* __restrict__ w2, const float* __restrict__ b2) {
    int id = blockIdx.x * blockDim.x + threadIdx.x;

    if (blockIdx.x < 26) {
        int idx = id;
        if (idx < 6400) {
            int which = idx >= 3200;
            int r = which ? idx - 3200 : idx;
            int kx = r % 5;
            int g  = r / 5;
            int ocic = g / 5;
            int ic  = ocic & 15;
            int ocp = ocic >> 4;
            int ky  = g % 5;
            const float* wsrc = which ? w2 : w1;
            float lo = wsrc[(2 * ocp) * 400 + ic * 25 + ky * 5 + kx];
            float hi = wsrc[(2 * ocp + 1) * 400 + ic * 25 + ky * 5 + kx];
            unsigned long long p;
            PACK2(p, lo, hi);
            if (kx < 4) { (which ? g_w2pa : g_w1pa)[g * 4 + kx] = p; }
            else        { (which ? g_w2pb : g_w1pb)[g]          = p; }
        } else if (idx < 6416) {
            int k = idx - 6400;
            int which = k >= 8;
            int p = k & 7;
            const float* bb = which ? b2 : b1;
            unsigned long long pr;
            PACK2(pr, bb[2 * p], bb[2 * p + 1]);
            (which ? g_b2p : g_b1p)[p] = pr;
        }
    }

    int pix = id & 4095;
    int oc  = (id >> 12) & 15;
    int b   = id >> 16;
    int py = pix >> 6, px = pix & 63;
    const float* xin = x + b * N_PIX;
    float acc = __ldg(bias + oc);
    #pragma unroll
    for (int ky = 0; ky < 5; ky++) {
        int gy = py + ky - 2;
        if (gy < 0 || gy >= IMG) continue;
        #pragma unroll
        for (int kx = 0; kx < 5; kx++) {
            int gx = px + kx - 2;
            if (gx < 0 || gx >= IMG) continue;
            acc = fmaf(xin[gy * IMG + gx], __ldg(w + oc * 25 + ky * 5 + kx), acc);
        }
    }
    g_buf0[id] = acc;
}

// ---------------- conv16: 256 threads = 4 ic-groups x (32x2 tile), grid (64,B) ----------------
template<bool FUSE>
__global__ void __launch_bounds__(256) conv16s_kernel() {
    __shared__ __align__(16) char smraw[39424];
    float* sin_t            = (float*)smraw;                         // 13824 B (16ch x 6 x 36)
    unsigned long long* swa = (unsigned long long*)(smraw + 13824);  // 20480 B
    unsigned long long* swb = (unsigned long long*)(smraw + 34304);  //  5120 B
    unsigned long long* sred = (unsigned long long*)(smraw + 13824); // overlay 12288 B

    const float* in = FUSE ? g_buf1 : g_buf0;
    const unsigned long long* gwa = FUSE ? g_w2pa : g_w1pa;
    const unsigned long long* gwb = FUSE ? g_w2pb : g_w1pb;
    const unsigned long long* gbp = FUSE ? g_b2p  : g_b1p;

    int tid  = threadIdx.x;
    int tile = blockIdx.x;                   // 0..63
    int b    = blockIdx.y;
    int tx0  = (tile & 1) * 32;
    int ty0  = (tile >> 1) * 2;

    for (int i = tid; i < 8 * 16 * 5 * 4; i += 256) swa[i] = gwa[i];
    for (int i = tid; i < 8 * 16 * 5;     i += 256) swb[i] = gwb[i];

    const float* inb = in + b * CH * N_PIX;
    for (int idx = tid; idx < CH * 6 * 36; idx += 256) {
        int c   = idx / 216;
        int rem = idx - c * 216;
        int r   = rem / 36;
        int cc  = rem - r * 36;
        int gy = ty0 + r - 2;
        int gx = tx0 + cc - 2;
        float v = 0.f;
        if (gy >= 0 && gy < IMG && gx >= 0 && gx < IMG)
            v = inb[c * N_PIX + gy * IMG + gx];
        sin_t[idx] = v;
    }
    __syncthreads();

    int grp = tid >> 6;         // 0..3: which 4 input channels
    int wg  = tid & 63;
    int tx = wg & 31, ty = wg >> 5;   // ty 0..1

    unsigned long long acc[8];
    #pragma unroll
    for (int p = 0; p < 8; p++) acc[p] = 0ULL;

    #pragma unroll
    for (int icl = 0; icl < 4; icl++) {
        int ic = grp * 4 + icl;
        const float* srow = &sin_t[ic * 216 + ty * 36 + tx];
        #pragma unroll
        for (int ky = 0; ky < 5; ky++) {
            const float* rr = srow + ky * 36;
            unsigned long long pa0, pa1, pa2, pa3, pa4;
            DUP2(pa0, rr[0]); DUP2(pa1, rr[1]); DUP2(pa2, rr[2]);
            DUP2(pa3, rr[3]); DUP2(pa4, rr[4]);
            #pragma unroll
            for (int p = 0; p < 8; p++) {
                int g = (p * 16 + ic) * 5 + ky;
                const ulonglong2* wq = reinterpret_cast<const ulonglong2*>(&swa[g * 4]);
                ulonglong2 q0 = wq[0];
                ulonglong2 q1 = wq[1];
                unsigned long long w4 = swb[g];
                FMA2(acc[p], pa0, q0.x);
                FMA2(acc[p], pa1, q0.y);
                FMA2(acc[p], pa2, q1.x);
                FMA2(acc[p], pa3, q1.y);
                FMA2(acc[p], pa4, w4);
            }
        }
    }

    __syncthreads();   // weights dead before overlay
    if (grp > 0) {
        #pragma unroll
        for (int p = 0; p < 8; p++)
            sred[p * 192 + (grp - 1) * 64 + wg] = acc[p];
    }
    __syncthreads();

    if (grp == 0) {
        #pragma unroll
        for (int p = 0; p < 8; p++) {
            ADD2(acc[p], sred[p * 192 + wg]);
            ADD2(acc[p], sred[p * 192 + 64 + wg]);
            ADD2(acc[p], sred[p * 192 + 128 + wg]);
            ADD2(acc[p], gbp[p]);
        }

        int py = ty0 + ty, px = tx0 + tx;
        int pix = py * IMG + px;

        if (!FUSE) {
            float* outb = g_buf1 + b * CH * N_PIX + pix;
            #pragma unroll
            for (int p = 0; p < 8; p++) {
                float lo, hi;
                UNPK2(lo, hi, acc[p]);
                outb[(2 * p) * N_PIX]     = lo;
                outb[(2 * p + 1) * N_PIX] = hi;
            }
        } else {
            // fused stats + pre-scale: xc' = (v - mean) * invstd * 0.25
            float v[16];
            float s = 0.f;
            #pragma unroll
            for (int p = 0; p < 8; p++) {
                UNPK2(v[2 * p], v[2 * p + 1], acc[p]);
                s += v[2 * p] + v[2 * p + 1];
            }
            float mean = s * (1.f / 16.f);
            float var = 0.f;
            #pragma unroll
            for (int c = 0; c < 16; c++) {
                float d = v[c] - mean;
                v[c] = d;
                var = fmaf(d, d, var);
            }
            var *= (1.f / 15.f);                 // ddof = 1
            float sc = rsqrtf(var) * 0.25f;      // 0.25^2 folds the /16
            float* xcb = g_xc + b * CH * N_PIX + pix;
            #pragma unroll
            for (int c = 0; c < 16; c++)
                xcb[c * N_PIX] = v[c] * sc;
        }
    }
}

// ---------------- coupling v4: r6 grid shape + r7 L1 cuts ----------------
// out[b,i,j] = (xc'_i . xc'_j) * mask   (xc' pre-scaled by invstd*0.25).
// Grid (B, 2080), b fastest -> mask tiles L2-resident across batches.
// tj >= ti only; mirror via conflict-free float4 staging (stride-17 rows,
// write-phase lane rotation). One batch per block: ~50 regs, high occupancy.
__global__ void __launch_bounds__(256) coupling_kernel(const float* __restrict__ mask,
                                                       float* __restrict__ out) {
    __shared__ __align__(16) float sxi[16 * 64];
    __shared__ __align__(16) float sxj[16 * 64];
    __shared__ __align__(16) float4 stg4[64 * 17];   // [jrow][icolgrp], stride 17

    int b = blockIdx.x;             // batch fastest
    int p = blockIdx.y;             // 0..2079 triangular pair index (T=64)

    int ti = (int)((129.0f - sqrtf(129.0f * 129.0f - 8.0f * (float)p)) * 0.5f);
    while (((ti + 1) * 64 - ((ti + 1) * ti) / 2) <= p) ti++;
    while ((ti * 64 - (ti * (ti - 1)) / 2) > p) ti--;
    int tj = ti + (p - (ti * 64 - (ti * (ti - 1)) / 2));
    bool diag = (ti == tj);

    int tid = threadIdx.x;
    const float* xcb = g_xc + b * CH * N_PIX;

    // fill sxi/sxj (16x64 each): 512 float4s over 256 threads
    #pragma unroll
    for (int it = 0; it < 2; it++) {
        int i = it * 256 + tid;
        int which = i >> 8;
        int k = i & 255;
        int c = k >> 4, q = k & 15;
        int t0 = which ? tj : ti;
        float4 v = *reinterpret_cast<const float4*>(xcb + c * N_PIX + t0 * 64 + q * 4);
        (which ? reinterpret_cast<float4*>(sxj) : reinterpret_cast<float4*>(sxi))[k] = v;
    }
    __syncthreads();

    int txj = tid & 15, tyi = tid >> 4;
    int jl = txj * 4, il = tyi * 4;

    unsigned long long a0[4], a1[4];
    #pragma unroll
    for (int ii = 0; ii < 4; ii++) { a0[ii] = 0ULL; a1[ii] = 0ULL; }

    #pragma unroll
    for (int c = 0; c < 16; c++) {
        float4 av = *reinterpret_cast<const float4*>(&sxi[c * 64 + il]);         // 1 LDS.128
        ulonglong2 bq = *reinterpret_cast<const ulonglong2*>(&sxj[c * 64 + jl]); // 1 LDS.128
        unsigned long long pa;
        DUP2(pa, av.x); FMA2(a0[0], pa, bq.x); FMA2(a1[0], pa, bq.y);
        DUP2(pa, av.y); FMA2(a0[1], pa, bq.x); FMA2(a1[1], pa, bq.y);
        DUP2(pa, av.z); FMA2(a0[2], pa, bq.x); FMA2(a1[2], pa, bq.y);
        DUP2(pa, av.w); FMA2(a0[3], pa, bq.x); FMA2(a1[3], pa, bq.y);
    }

    float v[4][4];
    #pragma unroll
    for (int ii = 0; ii < 4; ii++) {
        UNPK2(v[ii][0], v[ii][1], a0[ii]);
        UNPK2(v[ii][2], v[ii][3], a1[ii]);
    }

    size_t obase = (size_t)b * N_PIX * N_PIX;

    // forward stores (masked)
    #pragma unroll
    for (int ii = 0; ii < 4; ii++) {
        int ig = ti * 64 + il + ii;
        float4 m = *reinterpret_cast<const float4*>(mask + (size_t)ig * N_PIX + tj * 64 + jl);
        float* orow = out + obase + (size_t)ig * N_PIX + tj * 64 + jl;
        STG_CS4(orow, v[ii][0] * m.x, v[ii][1] * m.y, v[ii][2] * m.z, v[ii][3] * m.w);
    }

    if (!diag) {
        // staging: transposed float4 rows, lane-rotated for conflict-free phases
        #pragma unroll
        for (int k = 0; k < 4; k++) {
            int jj = (k + (txj >> 1)) & 3;
            stg4[(jl + jj) * 17 + tyi] =
                make_float4(v[0][jj], v[1][jj], v[2][jj], v[3][jj]);
        }
        __syncthreads();
        // mirror: rows tj*64+il+rr, cols ti*64+jl (coalesced)
        #pragma unroll
        for (int rr = 0; rr < 4; rr++) {
            float4 s = stg4[(il + rr) * 17 + txj];
            int jg = tj * 64 + il + rr;
            float4 m = *reinterpret_cast<const float4*>(mask + (size_t)jg * N_PIX + ti * 64 + jl);
            float* orow = out + obase + (size_t)jg * N_PIX + ti * 64 + jl;
            STG_CS4(orow, s.x * m.x, s.y * m.y, s.z * m.z, s.w * m.w);
        }
    }
}

// ---------------- launch ----------------
extern "C" void kernel_launch(void* const* d_in, const int* in_sizes, int n_in,
                              void* d_out, int out_size) {
    const float* x    = (const float*)d_in[0];
    const float* w0   = (const float*)d_in[1];
    const float* b0   = (const float*)d_in[2];
    const float* w1   = (const float*)d_in[3];
    const float* b1   = (const float*)d_in[4];
    const float* w2   = (const float*)d_in[5];
    const float* b2   = (const float*)d_in[6];
    const float* mask = (const float*)d_in[7];
    float* out = (float*)d_out;

    conv0_kernel<<<(B * CH * N_PIX) / 256, 256>>>(x, w0, b0, w1, b1, w2, b2);
    conv16s_kernel<false><<<dim3(64, B), 256>>>();      // g_buf0 -> g_buf1
    conv16s_kernel<true ><<<dim3(64, B), 256>>>();      // g_buf1 -> g_xc (pre-scaled)
    coupling_kernel<<<dim3(B, 2080), 256>>>(mask, out); // -> d_out
}